// round 11
// baseline (speedup 1.0000x reference)
#include <cuda_runtime.h>
#include <cuda_fp16.h>
#include <cstdint>

#define EPS_ 1e-4f

#define B_     2048
#define N_     64
#define E_     512
#define C_     6
#define CN_    7
#define K_     20
#define DSELF_ 120
#define DNEI_  48
#define ROWS_  (B_ * N_)        /* 131072 */
#define XSIZE_ (B_ * K_ * E_)   /* 20971520 */

#define TILE_M 64
#define NEI_B  2056             /* >= sum ceil(cnt_c/64) = 2048+6 */

#define BUCKET_B (ROWS_ / 256)  /* 512 */
#define ANCH_B   (C_ * K_)      /* 120 */
#define CONV_B   (CN_ * 8)      /* 56 */

// ---------------- device scratch ----------------
__device__ float g_anchor[C_ * K_ * E_];
__device__ int   g_cnt[CN_];
__device__ int   g_idx[CN_ * ROWS_];
__device__ int   g_nt;
__device__ int   g_done;
__device__ int2  g_tile[NEI_B];
__device__ __half g_Bh[CN_ * DNEI_ * E_];    // fp16 weights [c][k][e]

// ---------------- helpers ----------------
__device__ __forceinline__ uint32_t smem_u32(const void* p) {
    uint32_t a;
    asm("{ .reg .u64 t; cvta.to.shared.u64 t, %1; cvt.u32.u64 %0, t; }" : "=r"(a) : "l"(p));
    return a;
}
__device__ __forceinline__ float srecip(float x) {
    float d = x + (x >= 0.0f ? EPS_ : -EPS_);
    return __fdividef(1.0f, d);
}
__device__ __forceinline__ void ldsm4(uint32_t (&r)[4], uint32_t addr) {
    asm volatile("ldmatrix.sync.aligned.m8n8.x4.shared.b16 {%0,%1,%2,%3}, [%4];"
                 : "=r"(r[0]), "=r"(r[1]), "=r"(r[2]), "=r"(r[3]) : "r"(addr));
}
__device__ __forceinline__ void ldsm4t(uint32_t (&r)[4], uint32_t addr) {
    asm volatile("ldmatrix.sync.aligned.m8n8.x4.trans.shared.b16 {%0,%1,%2,%3}, [%4];"
                 : "=r"(r[0]), "=r"(r[1]), "=r"(r[2]), "=r"(r[3]) : "r"(addr));
}
__device__ __forceinline__ void mma_f16(float (&d)[4], const uint32_t (&a)[4],
                                        uint32_t b0, uint32_t b1) {
    asm volatile("mma.sync.aligned.m16n8k16.row.col.f32.f16.f16.f32 "
                 "{%0,%1,%2,%3}, {%4,%5,%6,%7}, {%8,%9}, {%0,%1,%2,%3};"
                 : "+f"(d[0]), "+f"(d[1]), "+f"(d[2]), "+f"(d[3])
                 : "r"(a[0]), "r"(a[1]), "r"(a[2]), "r"(a[3]), "r"(b0), "r"(b1));
}
__device__ __forceinline__ void cpa16(uint32_t dst, const void* src) {
    asm volatile("cp.async.cg.shared.global [%0], [%1], 16;" :: "r"(dst), "l"(src) : "memory");
}
#define CPA_COMMIT() asm volatile("cp.async.commit_group;" ::: "memory")
#define CPA_WAIT0()  asm volatile("cp.async.wait_group 0;" ::: "memory")

// ---------------- L1: zero flags ----------------
__global__ void k_zero() {
    if (threadIdx.x < CN_) g_cnt[threadIdx.x] = 0;
    if (threadIdx.x == CN_) g_done = 0;
}

// ---------------- L2: fused bucket + anchors + weight convert ----------------
__global__ void k_prebucket(const int* __restrict__ lab,
                            const float* __restrict__ it,
                            const float* __restrict__ Ws,
                            const float* __restrict__ bs,
                            const float* __restrict__ Wn) {
    int blk = blockIdx.x;
    int t   = threadIdx.x;

    if (blk < BUCKET_B) {
        // ---- bucket rows by neighbor label ----
        __shared__ int scnt[CN_], sbase[CN_];
        __shared__ int isLast;
        __shared__ int pfx[CN_ + 1];
        if (t < CN_) scnt[t] = 0;
        __syncthreads();
        int r = blk * 256 + t;
        int c = lab[r];
        int local = atomicAdd(&scnt[c], 1);
        __syncthreads();
        if (t < CN_) sbase[t] = atomicAdd(&g_cnt[t], scnt[t]);
        __syncthreads();
        g_idx[c * ROWS_ + sbase[c] + local] = r;

        __threadfence();
        if (t == 0) isLast = (atomicAdd(&g_done, 1) == BUCKET_B - 1);
        __syncthreads();
        if (!isLast) return;
        if (t == 0) {
            int off = 0;
            for (int cc = 0; cc < CN_; cc++) {
                pfx[cc] = off;
                off += (g_cnt[cc] + TILE_M - 1) / TILE_M;
            }
            pfx[CN_] = off;
            g_nt = off;
        }
        __syncthreads();
        int nt = pfx[CN_];
        for (int i = t; i < nt; i += blockDim.x) {
            int cc = 0;
            while (cc < CN_ - 1 && i >= pfx[cc + 1]) cc++;
            g_tile[i] = make_int2(cc, (i - pfx[cc]) * TILE_M);
        }
    } else if (blk < BUCKET_B + ANCH_B) {
        // ---- anchors: anchor[c,k,e] = it[c,k]·W_self[c,48:120,e] + b_self[c,e] ----
        __shared__ __align__(16) float its[72];
        int ck = blk - BUCKET_B;
        int c  = ck / K_;
        if (t < 18) ((float4*)its)[t] = ((const float4*)(it + ck * 72))[t];
        __syncthreads();
#pragma unroll
        for (int h = 0; h < 2; h++) {
            int e = t + h * 256;
            const float* W = Ws + c * DSELF_ * E_ + 48 * E_ + e;
            float a0 = 0.f, a1 = 0.f, a2 = 0.f, a3 = 0.f;
#pragma unroll
            for (int j = 0; j < 72; j += 4) {
                a0 += its[j + 0] * W[(j + 0) * E_];
                a1 += its[j + 1] * W[(j + 1) * E_];
                a2 += its[j + 2] * W[(j + 2) * E_];
                a3 += its[j + 3] * W[(j + 3) * E_];
            }
            g_anchor[ck * E_ + e] = (a0 + a1) + (a2 + a3) + bs[c * E_ + e];
        }
    } else {
        // ---- W_nei -> fp16 ----
        int pb = blk - BUCKET_B - ANCH_B;
        int c  = pb >> 3;
        int s  = pb & 7;
        const float* src = Wn + c * DNEI_ * E_;
        __half* dst = g_Bh + c * DNEI_ * E_;
        int base = s * 3072;
#pragma unroll
        for (int q = 0; q < 12; q++) {
            int i = base + q * 256 + t;
            dst[i] = __float2half_rn(src[i]);
        }
    }
}

// ---------------- L3: fused GEMM (blocks < NEI_B) + self embed (rest) ----------------
// nei smem: A [64 x 56 halves] = 7168 B ; B[2][48 x 72 halves] = 2x6912 B
#define ASTR_H 56
#define BSTR_H 72

__global__ void __launch_bounds__(128, 7)
k_main(const float* __restrict__ neis,
       const float* __restrict__ bn,
       const float* __restrict__ obs,
       const float* __restrict__ Ws,
       const int*   __restrict__ slab,
       float*       __restrict__ outx,
       float*       __restrict__ outn) {
    __shared__ __align__(16) __half Ash[TILE_M * ASTR_H];     // 7168 B
    __shared__ __align__(16) __half Bsh[2][DNEI_ * BSTR_H];   // 13824 B
    int tid = threadIdx.x;

    if (blockIdx.x >= NEI_B) {
        // ---------------- self embedding: one batch row per block ----------------
        float* osf = (float*)Ash;               // reuse smem (16B aligned)
        int b = blockIdx.x - NEI_B;
        if (tid < 12) ((float4*)osf)[tid] = ((const float4*)(obs + b * 48))[tid];
        int c = slab[b];
        __syncthreads();
        const float* W = Ws + c * DSELF_ * E_ + tid * 4;
        float4 acc = make_float4(0.f, 0.f, 0.f, 0.f);
#pragma unroll
        for (int j = 0; j < 48; j++) {
            float4 w = *(const float4*)(W + j * E_);
            float a = osf[j];
            acc.x += a * w.x; acc.y += a * w.y; acc.z += a * w.z; acc.w += a * w.w;
        }
        const float4* ap = (const float4*)(g_anchor + c * K_ * E_) + tid;
        float4* o = (float4*)(outx + b * K_ * E_) + tid;
#pragma unroll
        for (int k = 0; k < K_; k++) {
            float4 an = ap[k * (E_ / 4)];
            o[k * (E_ / 4)] = make_float4(acc.x + an.x, acc.y + an.y, acc.z + an.z, acc.w + an.w);
        }
        return;
    }

    // ---------------- neighbor GEMM tile ----------------
    if (blockIdx.x >= g_nt) return;
    int2 tl  = g_tile[blockIdx.x];
    int c    = tl.x;
    int base = tl.y;
    int cnt  = g_cnt[c];

    uint32_t sbA = smem_u32(Ash);
    uint32_t sbB = smem_u32(Bsh);

    // prefetch B[0] (e-chunk 0): 48 x 64 halves = 384 x 16B
    {
        const __half* gb = g_Bh + c * DNEI_ * E_;
#pragma unroll
        for (int p = 0; p < 3; p++) {
            int chunk = p * 128 + tid;
            int k  = chunk >> 3;
            int cc = chunk & 7;
            cpa16(sbB + k * (BSTR_H * 2) + cc * 16, gb + k * E_ + cc * 8);
        }
        CPA_COMMIT();
    }

    // A tile: gather + srecip + fp16 (once per CTA)
#pragma unroll
    for (int p = 0; p < 6; p++) {
        int lin = p * 128 + tid;          // 0..767
        int row = lin / 12;
        int v   = lin - row * 12;
        int gi  = base + row;
        float4 a = make_float4(0.f, 0.f, 0.f, 0.f);
        if (gi < cnt) {
            int rr = g_idx[c * ROWS_ + gi];
            a = ((const float4*)(neis + (long long)rr * 48))[v];
            a.x = srecip(a.x); a.y = srecip(a.y); a.z = srecip(a.z); a.w = srecip(a.w);
        }
        __half2* dst = (__half2*)(Ash + row * ASTR_H + v * 4);
        dst[0] = __halves2half2(__float2half_rn(a.x), __float2half_rn(a.y));
        dst[1] = __halves2half2(__float2half_rn(a.z), __float2half_rn(a.w));
    }

    // lane mapping: 4 warps = 2(wm) x 2(wn), warp tile 32x32
    int w    = tid >> 5;
    int lane = tid & 31;
    int wm   = w >> 1;
    int wn   = w & 1;

    int rowL = wm * 32 + ((lane >> 3) & 1) * 8 + (lane & 7);
    int kLa  = (lane >> 4) * 8;
    uint32_t aLane = sbA + (uint32_t)(rowL * (ASTR_H * 2) + kLa * 2);
    int kLb = ((lane >> 3) & 1) * 8 + (lane & 7);
    int nLb = (lane >> 4) * 8;
    uint32_t bLaneBase = sbB + (uint32_t)(kLb * (BSTR_H * 2) + (wn * 32 + nLb) * 2);

    // epilogue row indices
    int qr = lane >> 2;
    int qc = (lane & 3) * 2;
    int rg_[4];
    bool val_[4];
#pragma unroll
    for (int mi = 0; mi < 2; mi++) {
#pragma unroll
        for (int hf = 0; hf < 2; hf++) {
            int gi = base + wm * 32 + mi * 16 + hf * 8 + qr;
            val_[mi * 2 + hf] = gi < cnt;
            rg_[mi * 2 + hf]  = (gi < cnt) ? g_idx[c * ROWS_ + gi] : 0;
        }
    }

    // loop over 8 e-chunks of 64
#pragma unroll
    for (int et = 0; et < 8; et++) {
        CPA_WAIT0();
        __syncthreads();

        if (et < 7) {
            const __half* gb = g_Bh + c * DNEI_ * E_ + (et + 1) * 64;
            uint32_t dstb = sbB + ((et + 1) & 1) * (DNEI_ * BSTR_H * 2);
#pragma unroll
            for (int p = 0; p < 3; p++) {
                int chunk = p * 128 + tid;
                int k  = chunk >> 3;
                int cc = chunk & 7;
                cpa16(dstb + k * (BSTR_H * 2) + cc * 16, gb + k * E_ + cc * 8);
            }
            CPA_COMMIT();
        }

        // accumulators initialized from bias (epilogue add eliminated)
        int e0 = et << 6;
        const float* bp = bn + c * E_ + e0 + wn * 32 + qc;
        float acc[8][4];
#pragma unroll
        for (int ni = 0; ni < 4; ni++) {
            float bx = bp[ni * 8], by = bp[ni * 8 + 1];
#pragma unroll
            for (int mi = 0; mi < 2; mi++) {
                acc[mi * 4 + ni][0] = bx; acc[mi * 4 + ni][1] = by;
                acc[mi * 4 + ni][2] = bx; acc[mi * 4 + ni][3] = by;
            }
        }

        uint32_t bLane = bLaneBase + (et & 1) * (DNEI_ * BSTR_H * 2);
#pragma unroll
        for (int ks = 0; ks < 3; ks++) {
            uint32_t af[2][4], bfr[2][4];
#pragma unroll
            for (int mi = 0; mi < 2; mi++)
                ldsm4(af[mi], aLane + mi * 16 * (ASTR_H * 2) + ks * 32);
#pragma unroll
            for (int ng = 0; ng < 2; ng++)
                ldsm4t(bfr[ng], bLane + ks * 16 * (BSTR_H * 2) + ng * 32);
#pragma unroll
            for (int mi = 0; mi < 2; mi++) {
#pragma unroll
                for (int ni = 0; ni < 4; ni++)
                    mma_f16(acc[mi * 4 + ni], af[mi],
                            bfr[ni >> 1][(ni & 1) * 2], bfr[ni >> 1][(ni & 1) * 2 + 1]);
            }
        }

        // epilogue: scatter stores only
#pragma unroll
        for (int mi = 0; mi < 2; mi++) {
#pragma unroll
            for (int hf = 0; hf < 2; hf++) {
                if (val_[mi * 2 + hf]) {
                    float* o = outn + (long long)rg_[mi * 2 + hf] * E_ + e0 + wn * 32 + qc;
#pragma unroll
                    for (int ni = 0; ni < 4; ni++) {
                        float2 v;
                        v.x = acc[mi * 4 + ni][hf * 2 + 0];
                        v.y = acc[mi * 4 + ni][hf * 2 + 1];
                        *(float2*)(o + ni * 8) = v;
                    }
                }
            }
        }
    }
}

// ---------------- launch ----------------
extern "C" void kernel_launch(void* const* d_in, const int* in_sizes, int n_in,
                              void* d_out, int out_size) {
    const float* obs  = (const float*)d_in[0];
    const float* neis = (const float*)d_in[1];
    const float* it   = (const float*)d_in[2];
    const float* Ws   = (const float*)d_in[3];
    const float* bs   = (const float*)d_in[4];
    const float* Wn   = (const float*)d_in[5];
    const float* bn   = (const float*)d_in[6];
    const int*   slab = (const int*)d_in[7];
    const int*   nlab = (const int*)d_in[8];

    float* outx = (float*)d_out;            // [B, K, E]
    float* outn = outx + XSIZE_;            // [B, N, E]

    k_zero<<<1, 32>>>();
    k_prebucket<<<BUCKET_B + ANCH_B + CONV_B, 256>>>(nlab, it, Ws, bs, Wn);
    k_main<<<NEI_B + B_, 128>>>(neis, bn, obs, Ws, slab, outx, outn);
}